// round 5
// baseline (speedup 1.0000x reference)
#include <cuda_runtime.h>
#include <cuda_bf16.h>
#include <cstdint>

// Problem constants (max sizes for static scratch)
#define N_MAX 100000
#define E_MAX 1000000
#define NB_MAX 128           // ceil(N_MAX/1024) = 98 <= 128

// ---------------- device scratch (static allocation; no cudaMalloc) ----------------
// NOTE: these are ONLY referenced from device code. Never passed from host.
__device__ int   g_cnt[N_MAX];
__device__ int   g_rowptr[N_MAX + 1];
__device__ int   g_cursor[N_MAX];
__device__ int   g_csr_src[E_MAX];
__device__ int   g_bsum[NB_MAX];
__device__ float g_agg[(size_t)N_MAX * 64];
__device__ float g_h[(size_t)N_MAX * 64];

// ---------------- CSR build ----------------
__global__ void zero_k(int n) {
    int i = blockIdx.x * blockDim.x + threadIdx.x;
    if (i < n) g_cnt[i] = 0;
}

// edge_index is int32 (JAX without x64 silently downcasts int64 -> int32)
__global__ void count_k(const int* __restrict__ dst, int e, int n) {
    int i = blockIdx.x * blockDim.x + threadIdx.x;
    if (i < e) {
        int d = dst[i];
        if ((unsigned)d < (unsigned)n) atomicAdd(&g_cnt[d], 1);
    }
}

// per-block (1024 items) reduction into g_bsum
__global__ void scan1_k(int n) {
    int base = blockIdx.x * 1024;
    int t = threadIdx.x;
    int i0 = base + t * 4;
    int s = 0;
#pragma unroll
    for (int j = 0; j < 4; j++) {
        int i = i0 + j;
        if (i < n) s += g_cnt[i];
    }
#pragma unroll
    for (int o = 16; o; o >>= 1) s += __shfl_down_sync(0xffffffffu, s, o);
    __shared__ int ws[8];
    if ((t & 31) == 0) ws[t >> 5] = s;
    __syncthreads();
    if (t == 0) {
        int tot = 0;
#pragma unroll
        for (int j = 0; j < 8; j++) tot += ws[j];
        g_bsum[blockIdx.x] = tot;
    }
}

// exclusive scan of block sums (nb <= 128), one block of 128 threads
__global__ void scan2_k(int nb, int n, int e) {
    __shared__ int s[128];
    int t = threadIdx.x;
    int v = (t < nb) ? g_bsum[t] : 0;
    s[t] = v;
    __syncthreads();
    for (int o = 1; o < 128; o <<= 1) {
        int x = 0;
        if (t >= o) x = s[t - o];
        __syncthreads();
        s[t] += x;
        __syncthreads();
    }
    if (t < nb) g_bsum[t] = s[t] - v;   // exclusive
    if (t == 0) g_rowptr[n] = e;
}

// full exclusive scan: rowptr + cursor
__global__ void scan3_k(int n) {
    int base = blockIdx.x * 1024;
    int t = threadIdx.x;
    int lane = t & 31, wid = t >> 5;
    int i0 = base + t * 4;
    int v[4];
    int tsum = 0;
#pragma unroll
    for (int j = 0; j < 4; j++) {
        v[j] = (i0 + j < n) ? g_cnt[i0 + j] : 0;
        tsum += v[j];
    }
    int incl = tsum;
#pragma unroll
    for (int o = 1; o < 32; o <<= 1) {
        int u = __shfl_up_sync(0xffffffffu, incl, o);
        if (lane >= o) incl += u;
    }
    __shared__ int ws[8];
    if (lane == 31) ws[wid] = incl;
    __syncthreads();
    if (t < 8) {
        int u = ws[t];
        int inc = u;
#pragma unroll
        for (int o = 1; o < 8; o <<= 1) {
            int q = __shfl_up_sync(0xffu, inc, o);
            if (t >= o) inc += q;
        }
        ws[t] = inc - u;  // exclusive warp offset
    }
    __syncthreads();
    int excl = incl - tsum + ws[wid] + g_bsum[blockIdx.x];
#pragma unroll
    for (int j = 0; j < 4; j++) {
        int i = i0 + j;
        if (i < n) {
            g_rowptr[i] = excl;
            g_cursor[i] = excl;
            excl += v[j];
        }
    }
}

__global__ void fill_k(const int* __restrict__ src, const int* __restrict__ dst,
                       int e, int n) {
    int i = blockIdx.x * blockDim.x + threadIdx.x;
    if (i < e) {
        int d = dst[i];
        int s = src[i];
        if ((unsigned)d < (unsigned)n && (unsigned)s < (unsigned)n) {
            int pos = atomicAdd(&g_cursor[d], 1);
            g_csr_src[pos] = s;
        }
    }
}

// ---------------- aggregation: warp per node, mean of neighbor rows ----------------
// USE_H=false: feat = xin (harness input). USE_H=true: feat = g_h.
// Output always g_agg.
template <bool USE_H>
__global__ void __launch_bounds__(256)
agg_k(const float* __restrict__ xin, int n) {
    const float* feat = USE_H ? (const float*)g_h : xin;
    int warp = (blockIdx.x * blockDim.x + threadIdx.x) >> 5;
    int lane = threadIdx.x & 31;
    if (warp >= n) return;
    int beg = g_rowptr[warp];
    int end = g_rowptr[warp + 1];
    float a0 = 0.f, a1 = 0.f;
    int p = beg;
    for (; p + 1 < end; p += 2) {
        int s0 = g_csr_src[p];
        int s1 = g_csr_src[p + 1];
        const float* r0 = feat + (size_t)s0 * 64;
        const float* r1 = feat + (size_t)s1 * 64;
        float u0 = r0[lane], u1 = r0[lane + 32];
        float v0 = r1[lane], v1 = r1[lane + 32];
        a0 += u0 + v0;
        a1 += u1 + v1;
    }
    if (p < end) {
        int s0 = g_csr_src[p];
        const float* r0 = feat + (size_t)s0 * 64;
        a0 += r0[lane];
        a1 += r0[lane + 32];
    }
    int deg = end - beg;
    float inv = (deg > 0) ? (1.f / (float)deg) : 0.f;
    g_agg[(size_t)warp * 64 + lane] = a0 * inv;
    g_agg[(size_t)warp * 64 + 32 + lane] = a1 * inv;
}

// ---------------- fused linear: C = agg@W1^T + A2@W2^T + b (optional relu) ----------------
// A1 is always g_agg. A2 = USE_H ? g_h : xin. C = OUT_GLOBAL ? g_h : outp.
// Tile: 64 rows x 64 cols, K=128. 256 threads, 4x4 micro-tile, padded pitch 68.
#define GP 68

template <bool RELU, bool USE_H, bool OUT_GLOBAL>
__global__ void __launch_bounds__(256)
fused_linear(const float* __restrict__ xin,
             const float* __restrict__ W1, const float* __restrict__ W2,
             const float* __restrict__ bias, float* __restrict__ outp, int M) {
    const float* A1 = (const float*)g_agg;
    const float* A2 = USE_H ? (const float*)g_h : xin;
    float* C = OUT_GLOBAL ? (float*)g_h : outp;

    __shared__ __align__(16) float sW[128 * GP];  // sW[k*GP + o]
    __shared__ __align__(16) float sA[32 * GP];   // sA[k*GP + m]

    int tid = threadIdx.x;
    for (int idx = tid; idx < 4096; idx += 256) {
        int k = idx & 63;
        int o = idx >> 6;
        sW[k * GP + o] = W1[o * 64 + k];
        sW[(k + 64) * GP + o] = W2[o * 64 + k];
    }

    int m0 = blockIdx.x * 64;
    int tx = tid & 15;   // output-col group
    int ty = tid >> 4;   // row group
    float acc[4][4] = {};

    __syncthreads();

#pragma unroll
    for (int c = 0; c < 4; c++) {
        const float* Asrc = (c < 2) ? A1 : A2;
        int kb = (c & 1) * 32;
        __syncthreads();  // protect previous chunk reads
        for (int idx = tid; idx < 2048; idx += 256) {
            int k = idx & 31;
            int m = idx >> 5;
            int gm = m0 + m;
            float v = 0.f;
            if (gm < M) v = Asrc[(size_t)gm * 64 + kb + k];
            sA[k * GP + m] = v;
        }
        __syncthreads();
#pragma unroll
        for (int k = 0; k < 32; k++) {
            float4 a = *(const float4*)&sA[k * GP + ty * 4];
            float4 w = *(const float4*)&sW[(c * 32 + k) * GP + tx * 4];
            acc[0][0] += a.x * w.x; acc[0][1] += a.x * w.y; acc[0][2] += a.x * w.z; acc[0][3] += a.x * w.w;
            acc[1][0] += a.y * w.x; acc[1][1] += a.y * w.y; acc[1][2] += a.y * w.z; acc[1][3] += a.y * w.w;
            acc[2][0] += a.z * w.x; acc[2][1] += a.z * w.y; acc[2][2] += a.z * w.z; acc[2][3] += a.z * w.w;
            acc[3][0] += a.w * w.x; acc[3][1] += a.w * w.y; acc[3][2] += a.w * w.z; acc[3][3] += a.w * w.w;
        }
    }

    float4 b4 = *(const float4*)&bias[tx * 4];
#pragma unroll
    for (int i = 0; i < 4; i++) {
        int gm = m0 + ty * 4 + i;
        if (gm < M) {
            float4 o;
            o.x = acc[i][0] + b4.x;
            o.y = acc[i][1] + b4.y;
            o.z = acc[i][2] + b4.z;
            o.w = acc[i][3] + b4.w;
            if (RELU) {
                o.x = fmaxf(o.x, 0.f);
                o.y = fmaxf(o.y, 0.f);
                o.z = fmaxf(o.z, 0.f);
                o.w = fmaxf(o.w, 0.f);
            }
            *(float4*)&C[(size_t)gm * 64 + tx * 4] = o;
        }
    }
}

// ---------------- launcher ----------------
extern "C" void kernel_launch(void* const* d_in, const int* in_sizes, int n_in,
                              void* d_out, int out_size) {
    const float* x   = (const float*)d_in[0];
    const int*   ei  = (const int*)d_in[1];     // int32! (JAX x64 disabled)
    const float* W1l = (const float*)d_in[2];
    const float* b1  = (const float*)d_in[3];
    const float* W1r = (const float*)d_in[4];
    const float* W2l = (const float*)d_in[5];
    const float* b2  = (const float*)d_in[6];
    const float* W2r = (const float*)d_in[7];
    float* out = (float*)d_out;

    int n = in_sizes[0] / 64;
    int e = in_sizes[1] / 2;
    if (n > N_MAX) n = N_MAX;
    if (e > E_MAX) e = E_MAX;

    const int* src = ei;
    const int* dst = ei + e;

    int nb = (n + 1023) / 1024;

    // CSR build (by dst)
    zero_k<<<(n + 255) / 256, 256>>>(n);
    count_k<<<(e + 255) / 256, 256>>>(dst, e, n);
    scan1_k<<<nb, 256>>>(n);
    scan2_k<<<1, 128>>>(nb, n, e);
    scan3_k<<<nb, 256>>>(n);
    fill_k<<<(e + 255) / 256, 256>>>(src, dst, e, n);

    // Layer 1: agg(x) -> g_agg; g_h = relu(g_agg@W1l^T + b1 + x@W1r^T)
    agg_k<false><<<(n + 7) / 8, 256>>>(x, n);
    fused_linear<true, false, true><<<(n + 63) / 64, 256>>>(x, W1l, W1r, b1, nullptr, n);

    // Layer 2: agg(g_h) -> g_agg; out = g_agg@W2l^T + b2 + g_h@W2r^T
    agg_k<true><<<(n + 7) / 8, 256>>>(nullptr, n);
    fused_linear<false, true, false><<<(n + 63) / 64, 256>>>(nullptr, W2l, W2r, b2, out, n);
}